// round 4
// baseline (speedup 1.0000x reference)
#include <cuda_runtime.h>
#include <math.h>

// Problem constants
#define B_  8
#define A_  6
#define QS_ 32
#define KS_ 1024
#define C_  256
#define H_  64
#define W_DIM 64
#define NSPAT (C_ * H_ * W_DIM)            // 1048576 per (b, agent)
#define N4 (NSPAT / 4)                     // 262144 float4 per (b, agent)
#define OUT_MAIN ((size_t)B_ * A_ * NSPAT) // 50331648

// Allocation-free scratch (device global)
__device__ float g_attn[B_ * A_ * A_];     // softmaxed attention [B][K][Q]

// --------------------------------------------------------------------------
// Fused attention kernel: one block per batch, 1024 threads (32 warps).
//   kp[kk][j] = sum_d k[b,kk,d] * W[d,j]     (warp w owns d-slice w*32..w*32+31;
//                                             lane j reads W[d, j] -> 1 coalesced
//                                             128B line per LDG, 32 indep LDGs)
//   kb[kk]    = sum_d k[b,kk,d] * bias[d]
//   attn[kk][qq] = softmax_kk( kb[kk] + dot32(kp[kk], qu[b,qq]) )
// --------------------------------------------------------------------------
__global__ void __launch_bounds__(1024)
attn_fused_kernel(const float* __restrict__ qu,    // [B, A, QS]
                  const float* __restrict__ kmat,  // [B, A, KS]
                  const float* __restrict__ Wm,    // [KS, QS]
                  const float* __restrict__ bias,  // [KS]
                  float* __restrict__ out_tail,    // [B, A, A]
                  int write_tail) {
    const int b    = blockIdx.x;
    const int tid  = threadIdx.x;
    const int warp = tid >> 5;     // 0..31
    const int lane = tid & 31;

    __shared__ float s_k[A_ * KS_];            // 24 KB: k for this batch
    __shared__ float s_part[32][A_][QS_];      // 24 KB: per-warp kp partials
    __shared__ float s_kp[A_][QS_];
    __shared__ float s_kb[A_];
    __shared__ float s_attn[A_ * A_];

    // Stage k[b] (6144 floats = 1536 float4) cooperatively -> bulk MLP
    {
        const float4* __restrict__ kg = (const float4*)(kmat + (size_t)b * A_ * KS_);
        float4* sk4 = (float4*)s_k;
        #pragma unroll
        for (int i = tid; i < A_ * KS_ / 4; i += 1024) sk4[i] = kg[i];
    }
    __syncthreads();

    // Each warp: d-slice [warp*32, warp*32+32). Lane j: partial kp over slice.
    {
        float acc[A_] = {0.f, 0.f, 0.f, 0.f, 0.f, 0.f};
        const int d0 = warp * 32;
        #pragma unroll 8
        for (int i = 0; i < 32; i++) {
            const int d = d0 + i;
            const float wv = Wm[(size_t)d * QS_ + lane];   // coalesced, 1 line/warp
            #pragma unroll
            for (int kk = 0; kk < A_; kk++)
                acc[kk] = fmaf(s_k[kk * KS_ + d], wv, acc[kk]);  // smem broadcast
        }
        #pragma unroll
        for (int kk = 0; kk < A_; kk++)
            s_part[warp][kk][lane] = acc[kk];
    }

    // kb: warps 0..5 each dot(k[kk], bias) over 1024 (coalesced bias LDG)
    if (warp < A_) {
        float s = 0.f;
        #pragma unroll 8
        for (int i = 0; i < KS_ / 32; i++) {
            const int d = lane + 32 * i;
            s = fmaf(s_k[warp * KS_ + d], bias[d], s);
        }
        #pragma unroll
        for (int off = 16; off; off >>= 1)
            s += __shfl_down_sync(0xffffffffu, s, off);
        if (lane == 0) s_kb[warp] = s;
    }
    __syncthreads();

    // Reduce 32 warp-partials -> kp[6][32]  (192 threads, conflict-free)
    if (tid < A_ * QS_) {
        const int kk = tid >> 5, j = tid & 31;
        float acc = 0.f;
        #pragma unroll
        for (int w = 0; w < 32; w++) acc += s_part[w][kk][j];
        s_kp[kk][j] = acc;
    }
    __syncthreads();

    // scores[kk][qq] = kb[kk] + dot32(kp[kk], qu[b,qq,:])
    if (tid < A_ * A_) {
        const int kk = tid / A_, qq = tid % A_;
        const float* __restrict__ qrow = qu + ((size_t)b * A_ + qq) * QS_;
        float v = s_kb[kk];
        #pragma unroll
        for (int j = 0; j < QS_; j++) v = fmaf(s_kp[kk][j], qrow[j], v);
        s_attn[kk * A_ + qq] = v;
    }
    __syncthreads();

    // softmax over kk for each qq
    if (tid < A_) {
        const int qq = tid;
        float m = -INFINITY;
        #pragma unroll
        for (int kk = 0; kk < A_; kk++) m = fmaxf(m, s_attn[kk * A_ + qq]);
        float e[A_], sum = 0.f;
        #pragma unroll
        for (int kk = 0; kk < A_; kk++) {
            e[kk] = expf(s_attn[kk * A_ + qq] - m);
            sum += e[kk];
        }
        const float inv = 1.f / sum;
        #pragma unroll
        for (int kk = 0; kk < A_; kk++) {
            const float a = e[kk] * inv;
            g_attn[b * 36 + kk * A_ + qq] = a;
            if (write_tail) out_tail[b * 36 + kk * A_ + qq] = a;
        }
    }
}

// --------------------------------------------------------------------------
// Kernel C: out[b,q,x] = sum_k attn_sm[b,k,q] * v[b,k,x]  (x = c*h*w flat)
// HBM-bound streaming, ~78% DRAM. v loads issued BEFORE the s_a barrier so
// the 6 LDG.128 aren't serialized behind bar.sync.
// --------------------------------------------------------------------------
__global__ void __launch_bounds__(256)
combine_kernel(const float4* __restrict__ v, float4* __restrict__ out) {
    const int b = blockIdx.y;
    const int x = blockIdx.x * blockDim.x + threadIdx.x;   // 0 .. N4-1

    // Issue the big streaming loads first (independent of smem)
    float4 vv[A_];
    #pragma unroll
    for (int kk = 0; kk < A_; kk++)
        vv[kk] = v[((size_t)(b * A_ + kk)) * N4 + x];

    __shared__ float s_a[A_ * A_];
    if (threadIdx.x < A_ * A_) s_a[threadIdx.x] = g_attn[b * 36 + threadIdx.x];
    __syncthreads();

    #pragma unroll
    for (int qq = 0; qq < A_; qq++) {
        float4 o = make_float4(0.f, 0.f, 0.f, 0.f);
        #pragma unroll
        for (int kk = 0; kk < A_; kk++) {
            const float a = s_a[kk * A_ + qq];
            o.x = fmaf(a, vv[kk].x, o.x);
            o.y = fmaf(a, vv[kk].y, o.y);
            o.z = fmaf(a, vv[kk].z, o.z);
            o.w = fmaf(a, vv[kk].w, o.w);
        }
        out[((size_t)(b * A_ + qq)) * N4 + x] = o;
    }
}

extern "C" void kernel_launch(void* const* d_in, const int* in_sizes, int n_in,
                              void* d_out, int out_size) {
    const float* qu   = (const float*)d_in[0];   // [8,6,32]
    const float* kmat = (const float*)d_in[1];   // [8,6,1024]
    const float* v    = (const float*)d_in[2];   // [8,6,256,64,64]
    const float* Wm   = (const float*)d_in[3];   // [1024,32]
    const float* bias = (const float*)d_in[4];   // [1024]

    float* out = (float*)d_out;
    const int write_tail = ((size_t)out_size >= OUT_MAIN + (size_t)B_ * 36) ? 1 : 0;
    float* out_tail = out + OUT_MAIN;

    attn_fused_kernel<<<B_, 1024>>>(qu, kmat, Wm, bias, out_tail, write_tail);

    dim3 gridC(N4 / 256, B_);
    combine_kernel<<<gridC, 256>>>((const float4*)v, (float4*)out);
}

// round 5
// speedup vs baseline: 1.0550x; 1.0550x over previous
#include <cuda_runtime.h>
#include <math.h>

// Problem constants
#define B_  8
#define A_  6
#define QS_ 32
#define KS_ 1024
#define C_  256
#define H_  64
#define W_DIM 64
#define NSPAT (C_ * H_ * W_DIM)            // 1048576 per (b, agent)
#define N4 (NSPAT / 4)                     // 262144 float4 per (b, agent)
#define OUT_MAIN ((size_t)B_ * A_ * NSPAT) // 50331648

// Allocation-free scratch (device global)
__device__ float g_attn[B_ * A_ * A_];     // softmaxed attention [B][K][Q]

// --------------------------------------------------------------------------
// Primary kernel: fused attention (scores + softmax). One block per batch,
// 1024 threads. Signals dependent launch immediately so the combine grid
// can start its DRAM ramp while we compute.
// --------------------------------------------------------------------------
__global__ void __launch_bounds__(1024)
attn_fused_kernel(const float* __restrict__ qu,    // [B, A, QS]
                  const float* __restrict__ kmat,  // [B, A, KS]
                  const float* __restrict__ Wm,    // [KS, QS]
                  const float* __restrict__ bias,  // [KS]
                  float* __restrict__ out_tail,    // [B, A, A]
                  int write_tail) {
    // Let the dependent (combine) grid launch NOW — it only waits on our
    // completion at its griddepcontrol.wait.
    asm volatile("griddepcontrol.launch_dependents;");

    const int b    = blockIdx.x;
    const int tid  = threadIdx.x;
    const int warp = tid >> 5;     // 0..31
    const int lane = tid & 31;

    __shared__ float s_k[A_ * KS_];            // 24 KB
    __shared__ float s_part[32][A_][QS_];      // 24 KB
    __shared__ float s_kp[A_][QS_];
    __shared__ float s_kb[A_];
    __shared__ float s_attn[A_ * A_];

    // Stage k[b] cooperatively (1536 float4 -> bulk MLP)
    {
        const float4* __restrict__ kg = (const float4*)(kmat + (size_t)b * A_ * KS_);
        float4* sk4 = (float4*)s_k;
        #pragma unroll
        for (int i = tid; i < A_ * KS_ / 4; i += 1024) sk4[i] = kg[i];
    }
    __syncthreads();

    // Warp w owns d-slice [32w, 32w+32): lane j accumulates kp partials.
    {
        float acc[A_] = {0.f, 0.f, 0.f, 0.f, 0.f, 0.f};
        const int d0 = warp * 32;
        #pragma unroll 8
        for (int i = 0; i < 32; i++) {
            const int d = d0 + i;
            const float wv = Wm[(size_t)d * QS_ + lane];   // coalesced 128B line
            #pragma unroll
            for (int kk = 0; kk < A_; kk++)
                acc[kk] = fmaf(s_k[kk * KS_ + d], wv, acc[kk]);
        }
        #pragma unroll
        for (int kk = 0; kk < A_; kk++)
            s_part[warp][kk][lane] = acc[kk];
    }

    // kb: warps 0..5 each dot(k[kk], bias)
    if (warp < A_) {
        float s = 0.f;
        #pragma unroll 8
        for (int i = 0; i < KS_ / 32; i++) {
            const int d = lane + 32 * i;
            s = fmaf(s_k[warp * KS_ + d], bias[d], s);
        }
        #pragma unroll
        for (int off = 16; off; off >>= 1)
            s += __shfl_down_sync(0xffffffffu, s, off);
        if (lane == 0) s_kb[warp] = s;
    }
    __syncthreads();

    // Reduce 32 warp-partials -> kp[6][32]
    if (tid < A_ * QS_) {
        const int kk = tid >> 5, j = tid & 31;
        float acc = 0.f;
        #pragma unroll
        for (int w = 0; w < 32; w++) acc += s_part[w][kk][j];
        s_kp[kk][j] = acc;
    }
    __syncthreads();

    // scores[kk][qq] = kb[kk] + dot32(kp[kk], qu[b,qq,:])
    if (tid < A_ * A_) {
        const int kk = tid / A_, qq = tid % A_;
        const float* __restrict__ qrow = qu + ((size_t)b * A_ + qq) * QS_;
        float v = s_kb[kk];
        #pragma unroll
        for (int j = 0; j < QS_; j++) v = fmaf(s_kp[kk][j], qrow[j], v);
        s_attn[kk * A_ + qq] = v;
    }
    __syncthreads();

    // softmax over kk for each qq
    if (tid < A_) {
        const int qq = tid;
        float m = -INFINITY;
        #pragma unroll
        for (int kk = 0; kk < A_; kk++) m = fmaxf(m, s_attn[kk * A_ + qq]);
        float e[A_], sum = 0.f;
        #pragma unroll
        for (int kk = 0; kk < A_; kk++) {
            e[kk] = expf(s_attn[kk * A_ + qq] - m);
            sum += e[kk];
        }
        const float inv = 1.f / sum;
        #pragma unroll
        for (int kk = 0; kk < A_; kk++) {
            const float a = e[kk] * inv;
            g_attn[b * 36 + kk * A_ + qq] = a;
            if (write_tail) out_tail[b * 36 + kk * A_ + qq] = a;
        }
    }
}

// --------------------------------------------------------------------------
// Dependent kernel: out[b,q,x] = sum_k attn[b,k,q] * v[b,k,x].
// Prologue (v loads) overlaps the attn kernel via PDL; griddepcontrol.wait
// gates only the g_attn consumption. Streaming cache hints (cs) on both
// the 201MB read and 201MB write streams.
// --------------------------------------------------------------------------
__global__ void __launch_bounds__(256)
combine_kernel(const float4* __restrict__ v, float4* __restrict__ out) {
    const int b = blockIdx.y;
    const int x = blockIdx.x * blockDim.x + threadIdx.x;   // 0 .. N4-1

    // Independent prologue: issue the 6 big streaming loads (evict-first).
    float4 vv[A_];
    #pragma unroll
    for (int kk = 0; kk < A_; kk++)
        vv[kk] = __ldcs(&v[((size_t)(b * A_ + kk)) * N4 + x]);

    // Wait for the attn kernel (completion + memory flush).
    asm volatile("griddepcontrol.wait;" ::: "memory");

    __shared__ float s_a[A_ * A_];
    if (threadIdx.x < A_ * A_) s_a[threadIdx.x] = g_attn[b * 36 + threadIdx.x];
    __syncthreads();

    #pragma unroll
    for (int qq = 0; qq < A_; qq++) {
        float4 o = make_float4(0.f, 0.f, 0.f, 0.f);
        #pragma unroll
        for (int kk = 0; kk < A_; kk++) {
            const float a = s_a[kk * A_ + qq];
            o.x = fmaf(a, vv[kk].x, o.x);
            o.y = fmaf(a, vv[kk].y, o.y);
            o.z = fmaf(a, vv[kk].z, o.z);
            o.w = fmaf(a, vv[kk].w, o.w);
        }
        __stcs(&out[((size_t)(b * A_ + qq)) * N4 + x], o);
    }
}

extern "C" void kernel_launch(void* const* d_in, const int* in_sizes, int n_in,
                              void* d_out, int out_size) {
    const float* qu   = (const float*)d_in[0];   // [8,6,32]
    const float* kmat = (const float*)d_in[1];   // [8,6,1024]
    const float* v    = (const float*)d_in[2];   // [8,6,256,64,64]
    const float* Wm   = (const float*)d_in[3];   // [1024,32]
    const float* bias = (const float*)d_in[4];   // [1024]

    float* out = (float*)d_out;
    const int write_tail = ((size_t)out_size >= OUT_MAIN + (size_t)B_ * 36) ? 1 : 0;
    float* out_tail = out + OUT_MAIN;

    // Primary: attention (signals dependents early)
    attn_fused_kernel<<<B_, 1024>>>(qu, kmat, Wm, bias, out_tail, write_tail);

    // Dependent: combine, launched with Programmatic Stream Serialization
    // so its prologue overlaps the attn kernel.
    cudaLaunchConfig_t cfg = {};
    cfg.gridDim  = dim3(N4 / 256, B_, 1);
    cfg.blockDim = dim3(256, 1, 1);
    cfg.dynamicSmemBytes = 0;
    cfg.stream = 0;   // legacy default stream (the one under graph capture)
    cudaLaunchAttribute attr[1];
    attr[0].id = cudaLaunchAttributeProgrammaticStreamSerialization;
    attr[0].val.programmaticStreamSerializationAllowed = 1;
    cfg.attrs = attr;
    cfg.numAttrs = 1;
    cudaLaunchKernelEx(&cfg, combine_kernel, (const float4*)v, (float4*)out);
}